// round 5
// baseline (speedup 1.0000x reference)
#include <cuda_runtime.h>
#include <cuda_bf16.h>
#include <stdint.h>
#include <math.h>

typedef __nv_bfloat16 bf16;
typedef unsigned long long u64;
typedef unsigned int u32;

#define T_TOK 4096
#define HDIM  1024
#define IDIM  2048
#define NEXP  8
#define SLOTS (2 * T_TOK)

// ======================= scratch (device globals) =======================
__device__ __align__(16) bf16 g_xh[(size_t)T_TOK * HDIM];
__device__ __align__(16) bf16 g_xl[(size_t)T_TOK * HDIM];
__device__ __align__(16) bf16 g_tch[(size_t)T_TOK * HDIM];
__device__ __align__(16) bf16 g_tcl[(size_t)T_TOK * HDIM];
__device__ __align__(16) bf16 g_tpwT_h[(size_t)HDIM * HDIM];
__device__ __align__(16) bf16 g_tpwT_l[(size_t)HDIM * HDIM];
__device__ __align__(16) bf16 g_sgT_h[(size_t)IDIM * HDIM];
__device__ __align__(16) bf16 g_sgT_l[(size_t)IDIM * HDIM];
__device__ __align__(16) bf16 g_suT_h[(size_t)IDIM * HDIM];
__device__ __align__(16) bf16 g_suT_l[(size_t)IDIM * HDIM];
__device__ __align__(16) bf16 g_sdT_h[(size_t)HDIM * IDIM];
__device__ __align__(16) bf16 g_sdT_l[(size_t)HDIM * IDIM];
__device__ __align__(16) bf16 g_egT_h[(size_t)NEXP * IDIM * HDIM];
__device__ __align__(16) bf16 g_egT_l[(size_t)NEXP * IDIM * HDIM];
__device__ __align__(16) bf16 g_euT_h[(size_t)NEXP * IDIM * HDIM];
__device__ __align__(16) bf16 g_euT_l[(size_t)NEXP * IDIM * HDIM];
__device__ __align__(16) bf16 g_edT_h[(size_t)NEXP * HDIM * IDIM];
__device__ __align__(16) bf16 g_edT_l[(size_t)NEXP * HDIM * IDIM];

__device__ float g_xr[(size_t)T_TOK * HDIM];
__device__ float g_gbuf[(size_t)SLOTS * IDIM];
__device__ float g_ubuf[(size_t)SLOTS * IDIM];
__device__ __align__(16) bf16 g_hsh[(size_t)T_TOK * IDIM];
__device__ __align__(16) bf16 g_hsl[(size_t)T_TOK * IDIM];
__device__ __align__(16) bf16 g_hh[(size_t)SLOTS * IDIM];
__device__ __align__(16) bf16 g_hl[(size_t)SLOTS * IDIM];
__device__ float g_eout[(size_t)SLOTS * HDIM];

__device__ int   g_tok_e[T_TOK * 2];
__device__ float g_tok_w[T_TOK * 2];
__device__ int   g_tok_slot[T_TOK * 2];
__device__ int   g_counts[NEXP];
__device__ int   g_offsets[NEXP];
__device__ int   g_cursor[NEXP];
__device__ int   g_list_tok[SLOTS];
__device__ float g_list_w[SLOTS];

// ======================= PTX helpers (sm_80-era, compute_103-safe) =======================
__device__ __forceinline__ u32 smem_u32(const void* p) {
    u32 a;
    asm("{ .reg .u64 t; cvta.to.shared.u64 t, %1; cvt.u32.u64 %0, t; }" : "=r"(a) : "l"(p));
    return a;
}
__device__ __forceinline__ void cpa16(u32 dst, const void* src) {
    asm volatile("cp.async.cg.shared.global [%0], [%1], 16;"
                 :: "r"(dst), "l"(src) : "memory");
}
__device__ __forceinline__ void cpa_commit() {
    asm volatile("cp.async.commit_group;" ::: "memory");
}
__device__ __forceinline__ void cpa_wait1() {
    asm volatile("cp.async.wait_group 1;" ::: "memory");
}
__device__ __forceinline__ void ldsm4(u32* r, u32 addr) {
    asm volatile("ldmatrix.sync.aligned.m8n8.x4.shared.b16 {%0,%1,%2,%3}, [%4];"
                 : "=r"(r[0]), "=r"(r[1]), "=r"(r[2]), "=r"(r[3]) : "r"(addr));
}
__device__ __forceinline__ void mma_bf16(float* c, const u32* a, u32 b0, u32 b1) {
    asm volatile("mma.sync.aligned.m16n8k16.row.col.f32.bf16.bf16.f32 "
                 "{%0,%1,%2,%3}, {%4,%5,%6,%7}, {%8,%9}, {%0,%1,%2,%3};"
                 : "+f"(c[0]), "+f"(c[1]), "+f"(c[2]), "+f"(c[3])
                 : "r"(a[0]), "r"(a[1]), "r"(a[2]), "r"(a[3]), "r"(b0), "r"(b1));
}

// ======================= small kernels =======================
__global__ void k_init() {
    int i = threadIdx.x;
    if (i < NEXP) { g_counts[i] = 0; g_cursor[i] = 0; }
}

__global__ void k_split(const float* __restrict__ S, bf16* __restrict__ H,
                        bf16* __restrict__ L, int n4) {
    int i = blockIdx.x * blockDim.x + threadIdx.x;
    if (i >= n4) return;
    float4 v = ((const float4*)S)[i];
    union { bf16 b[4]; ushort4 u; } uh, ul;
    float vv[4] = { v.x, v.y, v.z, v.w };
#pragma unroll
    for (int j = 0; j < 4; j++) {
        bf16 h = __float2bfloat16(vv[j]);
        uh.b[j] = h;
        ul.b[j] = __float2bfloat16(vv[j] - __bfloat162float(h));
    }
    ((ushort4*)H)[i] = uh.u;
    ((ushort4*)L)[i] = ul.u;
}

// transpose + split: W [K,N] fp32 -> Th/Tl [N,K] bf16 (z = expert)
__global__ void k_tsplit(const float* __restrict__ W, bf16* __restrict__ Th,
                         bf16* __restrict__ Tl, int K, int N) {
    size_t eo = (size_t)blockIdx.z * K * N;
    W += eo; Th += eo; Tl += eo;
    __shared__ float t[32][33];
    int k0 = blockIdx.y * 32, n0 = blockIdx.x * 32;
    int tx = threadIdx.x, ty = threadIdx.y;  // 32 x 8
#pragma unroll
    for (int q = 0; q < 4; q++)
        t[ty + 8 * q][tx] = W[(size_t)(k0 + ty + 8 * q) * N + n0 + tx];
    __syncthreads();
#pragma unroll
    for (int q = 0; q < 4; q++) {
        int n = ty + 8 * q;
        float v = t[tx][n];
        bf16 h = __float2bfloat16(v);
        bf16 l = __float2bfloat16(v - __bfloat162float(h));
        size_t o = (size_t)(n0 + n) * K + k0 + tx;
        Th[o] = h; Tl[o] = l;
    }
}

__global__ void k_gate(const float* __restrict__ gw) {
    int t = (blockIdx.x * blockDim.x + threadIdx.x) >> 5;
    int lane = threadIdx.x & 31;
    if (t >= T_TOK) return;
    const float* xr = g_xr + (size_t)t * HDIM;
    float acc[8] = {0.f,0.f,0.f,0.f,0.f,0.f,0.f,0.f};
    for (int h = lane; h < HDIM; h += 32) {
        float xv = xr[h];
        float4 w0 = *(const float4*)(gw + (size_t)h * 8);
        float4 w1 = *(const float4*)(gw + (size_t)h * 8 + 4);
        acc[0] += xv * w0.x; acc[1] += xv * w0.y; acc[2] += xv * w0.z; acc[3] += xv * w0.w;
        acc[4] += xv * w1.x; acc[5] += xv * w1.y; acc[6] += xv * w1.z; acc[7] += xv * w1.w;
    }
#pragma unroll
    for (int o = 16; o; o >>= 1)
#pragma unroll
        for (int e = 0; e < 8; e++) acc[e] += __shfl_down_sync(0xffffffffu, acc[e], o);
    if (lane == 0) {
        float mx = acc[0];
#pragma unroll
        for (int e = 1; e < 8; e++) mx = fmaxf(mx, acc[e]);
        float p[8]; float Z = 0.f;
#pragma unroll
        for (int e = 0; e < 8; e++) { p[e] = __expf(acc[e] - mx); Z += p[e]; }
        float rZ = 1.f / Z;
#pragma unroll
        for (int e = 0; e < 8; e++) p[e] *= rZ;
        int i0 = 0; float p0 = p[0];
#pragma unroll
        for (int e = 1; e < 8; e++) if (p[e] > p0) { p0 = p[e]; i0 = e; }
        int i1 = -1; float p1 = -1.f;
#pragma unroll
        for (int e = 0; e < 8; e++) if (e != i0 && p[e] > p1) { p1 = p[e]; i1 = e; }
        float s = 1.f / (p0 + p1 + 1e-5f);
        g_tok_e[2*t] = i0;     g_tok_w[2*t] = p0 * s;
        g_tok_e[2*t+1] = i1;   g_tok_w[2*t+1] = p1 * s;
        atomicAdd(&g_counts[i0], 1); atomicAdd(&g_counts[i1], 1);
    }
}

__global__ void k_offsets() {
    if (threadIdx.x == 0) {
        int s = 0;
        for (int e = 0; e < NEXP; e++) { g_offsets[e] = s; s += g_counts[e]; g_cursor[e] = 0; }
    }
}

__global__ void k_place() {
    int t = blockIdx.x * blockDim.x + threadIdx.x;
    if (t >= T_TOK) return;
#pragma unroll
    for (int k = 0; k < 2; k++) {
        int e = g_tok_e[2*t + k];
        int pos = g_offsets[e] + atomicAdd(&g_cursor[e], 1);
        g_list_tok[pos] = t;
        g_list_w[pos] = g_tok_w[2*t + k];
        g_tok_slot[2*t + k] = pos;
    }
}

__global__ void k_silu(const float* __restrict__ G, const float* __restrict__ U,
                       bf16* __restrict__ Hh, bf16* __restrict__ Hl,
                       const float* __restrict__ wrow, int n4) {
    int i = blockIdx.x * blockDim.x + threadIdx.x;
    if (i >= n4) return;
    int row = i / (IDIM / 4);
    float w = wrow ? wrow[row] : 1.0f;
    float4 g = ((const float4*)G)[i];
    float4 u = ((const float4*)U)[i];
    float gg[4] = { g.x, g.y, g.z, g.w };
    float uu[4] = { u.x, u.y, u.z, u.w };
    union { bf16 b[4]; ushort4 us; } uh, ul;
#pragma unroll
    for (int j = 0; j < 4; j++) {
        float gv = gg[j];
        float sig = 1.f / (1.f + __expf(-gv));
        float h = w * (gv * sig) * uu[j];
        bf16 hb = __float2bfloat16(h);
        uh.b[j] = hb;
        ul.b[j] = __float2bfloat16(h - __bfloat162float(hb));
    }
    ((ushort4*)Hh)[i] = uh.us;
    ((ushort4*)Hl)[i] = ul.us;
}

__global__ void k_combine(float* __restrict__ out) {
    int gid = blockIdx.x * blockDim.x + threadIdx.x;
    int t = gid / (HDIM / 4);
    int c = (gid % (HDIM / 4)) * 4;
    if (t >= T_TOK) return;
    int s0 = g_tok_slot[2*t], s1 = g_tok_slot[2*t+1];
    float4 o = *(const float4*)(out + (size_t)t * HDIM + c);
    float4 a = *(const float4*)(g_eout + (size_t)s0 * HDIM + c);
    float4 b = *(const float4*)(g_eout + (size_t)s1 * HDIM + c);
    o.x += a.x + b.x; o.y += a.y + b.y; o.z += a.z + b.z; o.w += a.w + b.w;
    *(float4*)(out + (size_t)t * HDIM + c) = o;
}

// ======================= HMMA GEMM =======================
// C[M,N] = A @ B^T with bf16 hi/lo error compensation (3 or 4 passes).
// A [rows,K] hi/lo bf16; B pre-transposed [N,K] hi/lo bf16.
// CTA tile 128x128, K-chunk 32, 2-stage cp.async pipeline, 8 warps (warp tile 64x32).
// mode: 0 dense rows, 1 gathered (token list per expert), 2 slot rows (per expert)
// epi:  0 plain fp32 store, 1 router (+x +bias)

#define CH_K   32
#define ROWB   80                    // bytes per smem row (32 bf16 data + pad, 16B aligned)
#define MATB   (128 * ROWB)          // 10240 B per matrix tile
#define STGB   (4 * MATB)            // Ah, Al, Bh, Bl
#define GEMM_SMEM (2 * STGB)         // 81920 B

__global__ __launch_bounds__(256, 1) void k_gemm(
    const bf16* __restrict__ Ah, const bf16* __restrict__ Al,
    const bf16* __restrict__ Bh, const bf16* __restrict__ Bl,
    float* __restrict__ C, int Kdim, int Nld,
    int Mdense, int mode, int epi, int npass,
    const float* __restrict__ xadd, const float* __restrict__ bias)
{
    int cnt, off;
    if (mode == 0) { cnt = Mdense; off = 0; }
    else {
        int e = blockIdx.z;
        cnt = g_counts[e]; off = g_offsets[e];
        size_t wo = (size_t)e * Nld * Kdim;
        Bh += wo; Bl += wo;
    }
    const int m0 = blockIdx.y * 128;
    if (m0 >= cnt) return;
    const int n0 = blockIdx.x * 128;

    extern __shared__ char smem[];
    __shared__ int s_arow[128];
    const u32 sb = smem_u32(smem);
    const int tid = threadIdx.x;

    if (tid < 128) {
        int gr;
        if (mode == 0) gr = m0 + tid;
        else {
            int mr = m0 + tid; if (mr > cnt - 1) mr = cnt - 1;
            gr = (mode == 1) ? g_list_tok[off + mr] : (off + mr);
        }
        s_arow[tid] = gr;
    }
    __syncthreads();

    // loader: 4 matrices x 64 threads; each thread: 2 rows x 4 x 16B
    const int lmat = tid >> 6;
    const int lrow0 = (tid & 63) * 2;
    const bf16* lbase = (lmat == 0) ? Ah : (lmat == 1) ? Al : (lmat == 2) ? Bh : Bl;
    const bool lisA = lmat < 2;

    const int nc = Kdim / CH_K;

#define LOAD_STAGE(c) do {                                                   \
        int _k0 = (c) * CH_K;                                                \
        u32 _db = sb + ((c) & 1) * STGB + lmat * MATB;                       \
        _Pragma("unroll")                                                    \
        for (int _rr = 0; _rr < 2; _rr++) {                                  \
            int _row = lrow0 + _rr;                                          \
            int _gr = lisA ? s_arow[_row] : (n0 + _row);                     \
            const bf16* _p = lbase + (size_t)_gr * Kdim + _k0;               \
            u32 _d = _db + _row * ROWB;                                      \
            cpa16(_d,      _p);                                              \
            cpa16(_d + 16, _p + 8);                                          \
            cpa16(_d + 32, _p + 16);                                         \
            cpa16(_d + 48, _p + 24);                                         \
        }                                                                    \
    } while (0)

    float acc[4][4][4];
#pragma unroll
    for (int i = 0; i < 4; i++)
#pragma unroll
        for (int j = 0; j < 4; j++)
#pragma unroll
            for (int q = 0; q < 4; q++) acc[i][j][q] = 0.f;

    const int wid = tid >> 5, lane = tid & 31;
    const int wm = wid >> 2, wn = wid & 3;      // warp grid 2 x 4 -> 64 x 32 tile

    // per-lane ldmatrix address components
    const int a_r = wm * 64 + (lane & 15);       // + i*16
    const int a_kb = ((lane >> 4) & 1) * 16;     // byte: second 8-elem group
    const int b_g = lane >> 3, b_rl = lane & 7;
    const int b_nt = (b_g >> 1);                 // 0/1: which n8 tile within pair
    const int b_kb = (b_g & 1) * 16;

    LOAD_STAGE(0);
    cpa_commit();

    for (int c = 0; c < nc; c++) {
        if (c + 1 < nc) LOAD_STAGE(c + 1);
        cpa_commit();
        cpa_wait1();
        __syncthreads();

        const u32 ab = sb + (c & 1) * STGB;
        const u32 bb = ab + 2 * MATB;

#pragma unroll
        for (int kk = 0; kk < 2; kk++) {
            const int kbyte = kk * 32;
            u32 ahf[4][4], alf[4][4], bhf[2][4], blf[2][4];
#pragma unroll
            for (int i = 0; i < 4; i++) {
                u32 ad = ab + (a_r + i * 16) * ROWB + kbyte + a_kb;
                ldsm4(ahf[i], ad);
                ldsm4(alf[i], ad + MATB);
            }
#pragma unroll
            for (int j = 0; j < 2; j++) {
                int nr = wn * 32 + (j * 2 + b_nt) * 8 + b_rl;
                u32 bd = bb + nr * ROWB + kbyte + b_kb;
                ldsm4(bhf[j], bd);
                ldsm4(blf[j], bd + MATB);
            }
#pragma unroll
            for (int i = 0; i < 4; i++)
#pragma unroll
                for (int nt = 0; nt < 4; nt++) {
                    float* cc = acc[i][nt];
                    u32 bh0 = bhf[nt >> 1][(nt & 1) * 2], bh1 = bhf[nt >> 1][(nt & 1) * 2 + 1];
                    u32 bl0 = blf[nt >> 1][(nt & 1) * 2], bl1 = blf[nt >> 1][(nt & 1) * 2 + 1];
                    mma_bf16(cc, ahf[i], bh0, bh1);
                    mma_bf16(cc, ahf[i], bl0, bl1);
                    mma_bf16(cc, alf[i], bh0, bh1);
                    if (npass == 4) mma_bf16(cc, alf[i], bl0, bl1);
                }
        }
        __syncthreads();
    }

    // epilogue: thread holds acc[i][nt][{c0,c1,c2,c3}]
    //   rows: wm*64 + i*16 + lane/4 + {0,8};  cols: wn*32 + nt*8 + (lane%4)*2 + {0,1}
#pragma unroll
    for (int i = 0; i < 4; i++) {
#pragma unroll
        for (int h = 0; h < 2; h++) {
            int lr = wm * 64 + i * 16 + (lane >> 2) + h * 8;
            if (m0 + lr < cnt) {
                int orow = (mode == 0 ? 0 : off) + m0 + lr;
                float* crow = C + (size_t)orow * Nld + n0 + wn * 32;
                const float* xr = (epi == 1) ? (xadd + (size_t)(m0 + lr) * HDIM + n0 + wn * 32) : nullptr;
                const float* bs = (epi == 1) ? (bias + n0 + wn * 32) : nullptr;
#pragma unroll
                for (int nt = 0; nt < 4; nt++) {
                    int col = nt * 8 + (lane & 3) * 2;
                    float v0 = acc[i][nt][h * 2];
                    float v1 = acc[i][nt][h * 2 + 1];
                    if (epi == 1) {
                        v0 += xr[col] + bs[col];
                        v1 += xr[col + 1] + bs[col + 1];
                    }
                    *(float2*)(crow + col) = make_float2(v0, v1);
                }
            }
        }
    }
#undef LOAD_STAGE
}

// ======================= launch =======================
extern "C" void kernel_launch(void* const* d_in, const int* in_sizes, int n_in,
                              void* d_out, int out_size) {
    const float* x   = (const float*)d_in[0];
    const float* tcx = (const float*)d_in[1];
    const float* tpw = (const float*)d_in[2];
    const float* tpb = (const float*)d_in[3];
    const float* gw  = (const float*)d_in[4];
    const float* eg  = (const float*)d_in[5];
    const float* eu  = (const float*)d_in[6];
    const float* ed  = (const float*)d_in[7];
    const float* sg  = (const float*)d_in[8];
    const float* su  = (const float*)d_in[9];
    const float* sd  = (const float*)d_in[10];
    float* out = (float*)d_out;

    cudaFuncSetAttribute(k_gemm, cudaFuncAttributeMaxDynamicSharedMemorySize, GEMM_SMEM);

    bf16 *xh, *xl, *tch, *tcl, *tpwTh, *tpwTl, *sgTh, *sgTl, *suTh, *suTl,
         *sdTh, *sdTl, *egTh, *egTl, *euTh, *euTl, *edTh, *edTl,
         *hsh, *hsl, *hh, *hl;
    float *xr, *gbuf, *ubuf, *eout, *listw;
    cudaGetSymbolAddress((void**)&xh, g_xh);   cudaGetSymbolAddress((void**)&xl, g_xl);
    cudaGetSymbolAddress((void**)&tch, g_tch); cudaGetSymbolAddress((void**)&tcl, g_tcl);
    cudaGetSymbolAddress((void**)&tpwTh, g_tpwT_h); cudaGetSymbolAddress((void**)&tpwTl, g_tpwT_l);
    cudaGetSymbolAddress((void**)&sgTh, g_sgT_h); cudaGetSymbolAddress((void**)&sgTl, g_sgT_l);
    cudaGetSymbolAddress((void**)&suTh, g_suT_h); cudaGetSymbolAddress((void**)&suTl, g_suT_l);
    cudaGetSymbolAddress((void**)&sdTh, g_sdT_h); cudaGetSymbolAddress((void**)&sdTl, g_sdT_l);
    cudaGetSymbolAddress((void**)&egTh, g_egT_h); cudaGetSymbolAddress((void**)&egTl, g_egT_l);
    cudaGetSymbolAddress((void**)&euTh, g_euT_h); cudaGetSymbolAddress((void**)&euTl, g_euT_l);
    cudaGetSymbolAddress((void**)&edTh, g_edT_h); cudaGetSymbolAddress((void**)&edTl, g_edT_l);
    cudaGetSymbolAddress((void**)&hsh, g_hsh); cudaGetSymbolAddress((void**)&hsl, g_hsl);
    cudaGetSymbolAddress((void**)&hh, g_hh);   cudaGetSymbolAddress((void**)&hl, g_hl);
    cudaGetSymbolAddress((void**)&xr, g_xr);
    cudaGetSymbolAddress((void**)&gbuf, g_gbuf); cudaGetSymbolAddress((void**)&ubuf, g_ubuf);
    cudaGetSymbolAddress((void**)&eout, g_eout);
    cudaGetSymbolAddress((void**)&listw, g_list_w);

    k_init<<<1, 32>>>();

    // split activations into bf16 hi/lo
    {
        int n4 = T_TOK * HDIM / 4;
        k_split<<<n4 / 256, 256>>>(x, xh, xl, n4);
        k_split<<<n4 / 256, 256>>>(tcx, tch, tcl, n4);
    }
    // transpose+split weights
    k_tsplit<<<dim3(HDIM/32, HDIM/32, 1), dim3(32, 8)>>>(tpw, tpwTh, tpwTl, HDIM, HDIM);
    k_tsplit<<<dim3(IDIM/32, HDIM/32, 1), dim3(32, 8)>>>(sg, sgTh, sgTl, HDIM, IDIM);
    k_tsplit<<<dim3(IDIM/32, HDIM/32, 1), dim3(32, 8)>>>(su, suTh, suTl, HDIM, IDIM);
    k_tsplit<<<dim3(HDIM/32, IDIM/32, 1), dim3(32, 8)>>>(sd, sdTh, sdTl, IDIM, HDIM);
    k_tsplit<<<dim3(IDIM/32, HDIM/32, NEXP), dim3(32, 8)>>>(eg, egTh, egTl, HDIM, IDIM);
    k_tsplit<<<dim3(IDIM/32, HDIM/32, NEXP), dim3(32, 8)>>>(eu, euTh, euTl, HDIM, IDIM);
    k_tsplit<<<dim3(HDIM/32, IDIM/32, NEXP), dim3(32, 8)>>>(ed, edTh, edTl, IDIM, HDIM);

    // router: xr = x + tc @ tpw + b (4-pass for exact top-k)
    k_gemm<<<dim3(HDIM/128, T_TOK/128, 1), 256, GEMM_SMEM>>>(
        tch, tcl, tpwTh, tpwTl, xr, HDIM, HDIM, T_TOK, 0, 1, 4, x, tpb);

    k_gate<<<T_TOK / 8, 256>>>(gw);
    k_offsets<<<1, 32>>>();
    k_place<<<T_TOK / 256, 256>>>();

    // shared expert gate/up
    k_gemm<<<dim3(IDIM/128, T_TOK/128, 1), 256, GEMM_SMEM>>>(
        xh, xl, sgTh, sgTl, gbuf, HDIM, IDIM, T_TOK, 0, 0, 3, nullptr, nullptr);
    k_gemm<<<dim3(IDIM/128, T_TOK/128, 1), 256, GEMM_SMEM>>>(
        xh, xl, suTh, suTl, ubuf, HDIM, IDIM, T_TOK, 0, 0, 3, nullptr, nullptr);
    k_silu<<<(T_TOK * IDIM / 4) / 256, 256>>>(gbuf, ubuf, hsh, hsl, nullptr, T_TOK * IDIM / 4);

    // sparse experts gate/up (gathered rows)
    k_gemm<<<dim3(IDIM/128, SLOTS/128, NEXP), 256, GEMM_SMEM>>>(
        xh, xl, egTh, egTl, gbuf, HDIM, IDIM, 0, 1, 0, 3, nullptr, nullptr);
    k_gemm<<<dim3(IDIM/128, SLOTS/128, NEXP), 256, GEMM_SMEM>>>(
        xh, xl, euTh, euTl, ubuf, HDIM, IDIM, 0, 1, 0, 3, nullptr, nullptr);
    k_silu<<<(SLOTS * IDIM / 4) / 256, 256>>>(gbuf, ubuf, hh, hl, listw, SLOTS * IDIM / 4);

    // shared down -> out
    k_gemm<<<dim3(HDIM/128, T_TOK/128, 1), 256, GEMM_SMEM>>>(
        hsh, hsl, sdTh, sdTl, out, IDIM, HDIM, T_TOK, 0, 0, 3, nullptr, nullptr);
    // expert down -> per-slot scratch
    k_gemm<<<dim3(HDIM/128, SLOTS/128, NEXP), 256, GEMM_SMEM>>>(
        hh, hl, edTh, edTl, eout, IDIM, HDIM, 0, 2, 0, 3, nullptr, nullptr);

    k_combine<<<(T_TOK * (HDIM / 4)) / 256, 256>>>(out);
}